// round 6
// baseline (speedup 1.0000x reference)
#include <cuda_runtime.h>
#include <cstdint>

#define D 64
#define MAXN 100000
#define MAXE 1600000
#define MAXB 512   // max scan blocks: ceil(100000/256)=391 <= 512

// Scratch (device globals — PLAIN loads/stores only; atomics on module
// globals trap with cudaErrorInvalidAddressSpace in this environment).
__device__ __align__(16) float g_hn[(size_t)MAXN * D];   // neighbor mean
__device__ __align__(16) float g_h1[(size_t)MAXN * D];   // layer-1 output
__device__ int g_off[MAXN + 1];    // CSR row offsets
__device__ int g_bsum[MAXB];       // scan block sums
__device__ int g_eidx[MAXE];       // CSR column indices (source nodes)
__device__ int g_src[MAXE];        // converted src indices (int32)
__device__ int g_dst[MAXE];        // converted dst indices (int32)
__device__ int g_is64;             // 1 if index buffers are int64

// All atomics operate on `scratch` = (int*)d_out (harness-allocated):
//   scratch[0 .. N)   : histogram counts
//   scratch[N .. 2N)  : fill cursors
// Layer-2 GEMM later overwrites all of d_out with the real output.

// ---------------------------------------------------------------------------
// Dtype probe: if indices are int64 (values < 2^31), every odd 32-bit word
// is zero. For int32 random indices, some odd word among 1024 is nonzero.
// ---------------------------------------------------------------------------
__global__ void probe_kernel(const unsigned* __restrict__ raw, int E) {
    int nprobe = E < 1024 ? E : 1024;
    int any = 0;
    for (int i = 0; i < nprobe; i++) any |= raw[2 * i + 1];
    g_is64 = (any == 0) ? 1 : 0;
}

// Convert + clamp indices to int32 module-global arrays (plain stores).
__global__ void convert_kernel(const void* __restrict__ srcp,
                               const void* __restrict__ dstp, int E, int N) {
    int e = blockIdx.x * blockDim.x + threadIdx.x;
    if (e >= E) return;
    int s, d;
    if (g_is64) {
        s = (int)((const long long*)srcp)[e];
        d = (int)((const long long*)dstp)[e];
    } else {
        s = ((const int*)srcp)[e];
        d = ((const int*)dstp)[e];
    }
    s = s < 0 ? 0 : (s >= N ? N - 1 : s);
    d = d < 0 ? 0 : (d >= N ? N - 1 : d);
    g_src[e] = s;
    g_dst[e] = d;
}

// ---------------------------------------------------------------------------
__global__ void hist_zero_kernel(int* __restrict__ scratch, int N) {
    int i = blockIdx.x * blockDim.x + threadIdx.x;
    if (i < N) scratch[i] = 0;
}

// Histogram of dst (int atomics on harness-allocated memory)
__global__ void hist_kernel(int* __restrict__ scratch, int E) {
    int e = blockIdx.x * blockDim.x + threadIdx.x;
    if (e < E) atomicAdd(&scratch[g_dst[e]], 1);
}

// Per-block exclusive scan of counts (Hillis-Steele over 256)
__global__ void csr_scan1_kernel(const int* __restrict__ scratch, int N) {
    __shared__ int buf[2][256];
    int t = threadIdx.x;
    int i = blockIdx.x * 256 + t;
    int v = (i < N) ? scratch[i] : 0;
    buf[0][t] = v;
    __syncthreads();
    int p = 0;
    #pragma unroll
    for (int off = 1; off < 256; off <<= 1) {
        int val = buf[p][t] + ((t >= off) ? buf[p][t - off] : 0);
        buf[1 - p][t] = val;
        __syncthreads();
        p = 1 - p;
    }
    int incl = buf[p][t];
    if (i < N) g_off[i] = incl - v;          // block-local exclusive
    if (t == 255) g_bsum[blockIdx.x] = incl; // block total
}

// Single-block exclusive scan of block sums (nb <= 512)
__global__ void csr_scan2_kernel(int nb) {
    __shared__ int buf[2][MAXB];
    int t = threadIdx.x;
    int v = (t < nb) ? g_bsum[t] : 0;
    buf[0][t] = v;
    __syncthreads();
    int p = 0;
    for (int off = 1; off < MAXB; off <<= 1) {
        int val = buf[p][t] + ((t >= off) ? buf[p][t - off] : 0);
        buf[1 - p][t] = val;
        __syncthreads();
        p = 1 - p;
    }
    int incl = buf[p][t];
    if (t < nb) g_bsum[t] = incl - v;        // exclusive block prefix
}

// Add block prefixes; init fill cursors (in d_out scratch); write g_off[N]
__global__ void csr_scan3_kernel(int* __restrict__ cur, int N, int E) {
    int i = blockIdx.x * blockDim.x + threadIdx.x;
    if (i < N) {
        int o = g_off[i] + g_bsum[i >> 8];
        g_off[i] = o;
        cur[i] = o;
    }
    if (i == 0) g_off[N] = E;
}

// Fill CSR column indices (int atomics on harness-allocated cursors)
__global__ void csr_fill_kernel(int* __restrict__ cur, int E) {
    int e = blockIdx.x * blockDim.x + threadIdx.x;
    if (e < E) {
        int pos = atomicAdd(&cur[g_dst[e]], 1);
        if (pos >= 0 && pos < MAXE) g_eidx[pos] = g_src[e];
    }
}

// ---------------------------------------------------------------------------
// Gather-mean aggregation: 16 threads per node, each owns one float4 chunk.
// Feature LDG.128 covers 256B contiguous per edge; mean written once with
// a plain STG.128. No atomics, no scatter.
// ---------------------------------------------------------------------------
__global__ void gather_kernel(const float* __restrict__ x, int N, int use_h1) {
    const float* h = use_h1 ? (const float*)g_h1 : x;
    int gid = blockIdx.x * blockDim.x + threadIdx.x;
    int n = gid >> 4;
    if (n >= N) return;
    int c = (gid & 15) << 2;

    int beg = g_off[n];
    int end = g_off[n + 1];

    float ax = 0.0f, ay = 0.0f, az = 0.0f, aw = 0.0f;
    for (int j = beg; j < end; j++) {
        int s = g_eidx[j];
        float4 v = *reinterpret_cast<const float4*>(h + ((size_t)s << 6) + c);
        ax += v.x; ay += v.y; az += v.z; aw += v.w;
    }
    float inv = 1.0f / fmaxf((float)(end - beg), 1.0f);
    float4 r;
    r.x = ax * inv; r.y = ay * inv; r.z = az * inv; r.w = aw * inv;
    *reinterpret_cast<float4*>(g_hn + ((size_t)n << 6) + c) = r;
}

// ---------------------------------------------------------------------------
// Fused SAGE layer GEMM: out[r][c] = sum_k in[r][k]*Ws[k][c]
//                                  + hn[r][k]*Wn[k][c] + b[c]
// ---------------------------------------------------------------------------
__global__ void gemm_kernel(const float* __restrict__ x,
                            const float* __restrict__ Ws,
                            const float* __restrict__ Wn,
                            const float* __restrict__ b,
                            float* __restrict__ o,
                            int N, int ntiles, int use_h1, int out_is_h1) {
    const float* in = use_h1 ? (const float*)g_h1 : x;
    float* out      = out_is_h1 ? (float*)g_h1 : o;

    __shared__ float sWs[D * D];
    __shared__ float sWn[D * D];
    __shared__ float sb[D];
    __shared__ float sx[16][D];
    __shared__ float sh[16][D];

    for (int i = threadIdx.x; i < D * D; i += blockDim.x) {
        sWs[i] = Ws[i];
        sWn[i] = Wn[i];
    }
    if (threadIdx.x < D) sb[threadIdx.x] = b[threadIdx.x];
    __syncthreads();

    const int c    = threadIdx.x & 63;
    const int slot = threadIdx.x >> 6;

    for (int tile = blockIdx.x; tile < ntiles; tile += gridDim.x) {
        int base = tile * 16;

        for (int i = threadIdx.x; i < 16 * D; i += blockDim.x) {
            int rr = i >> 6, kk = i & 63;
            int row = base + rr;
            float vx = 0.0f, vh = 0.0f;
            if (row < N) {
                vx = in[((size_t)row << 6) + kk];
                vh = g_hn[((size_t)row << 6) + kk];
            }
            sx[rr][kk] = vx;
            sh[rr][kk] = vh;
        }
        __syncthreads();

        const int r0 = slot * 4;
        float acc0 = 0.0f, acc1 = 0.0f, acc2 = 0.0f, acc3 = 0.0f;
        #pragma unroll 8
        for (int k = 0; k < D; k++) {
            float ws = sWs[k * D + c];
            float wn = sWn[k * D + c];
            acc0 += sx[r0 + 0][k] * ws;  acc0 += sh[r0 + 0][k] * wn;
            acc1 += sx[r0 + 1][k] * ws;  acc1 += sh[r0 + 1][k] * wn;
            acc2 += sx[r0 + 2][k] * ws;  acc2 += sh[r0 + 2][k] * wn;
            acc3 += sx[r0 + 3][k] * ws;  acc3 += sh[r0 + 3][k] * wn;
        }

        float bias = sb[c];
        int row = base + r0;
        if (row + 0 < N) out[((size_t)(row + 0) << 6) + c] = acc0 + bias;
        if (row + 1 < N) out[((size_t)(row + 1) << 6) + c] = acc1 + bias;
        if (row + 2 < N) out[((size_t)(row + 2) << 6) + c] = acc2 + bias;
        if (row + 3 < N) out[((size_t)(row + 3) << 6) + c] = acc3 + bias;
        __syncthreads();
    }
}

// ---------------------------------------------------------------------------
// Launch: probe/convert + CSR build + 2 SAGE layers.
// Inputs: x, src, dst, W_self1, W_neigh1, b1, W_self2, W_neigh2, b2
// ---------------------------------------------------------------------------
extern "C" void kernel_launch(void* const* d_in, const int* in_sizes, int n_in,
                              void* d_out, int out_size) {
    const float* x   = (const float*)d_in[0];
    const void*  src = d_in[1];
    const void*  dst = d_in[2];
    const float* Ws1 = (const float*)d_in[3];
    const float* Wn1 = (const float*)d_in[4];
    const float* b1  = (const float*)d_in[5];
    const float* Ws2 = (const float*)d_in[6];
    const float* Wn2 = (const float*)d_in[7];
    const float* b2  = (const float*)d_in[8];
    float* out = (float*)d_out;

    int N = in_sizes[0] / D;
    int E = in_sizes[1];

    // Alias d_out as int scratch: [0..N) histogram, [N..2N) cursors.
    int* hist = (int*)d_out;
    int* cur  = ((int*)d_out) + N;

    const int TPB = 256;
    int ngrid = (N + TPB - 1) / TPB;          // also = number of scan blocks
    int egrid = (E + TPB - 1) / TPB;
    int ggrid = ((N * 16) + TPB - 1) / TPB;   // gather: 16 threads/node
    int ntiles = (N + 15) / 16;
    int mgrid = ntiles < 1480 ? ntiles : 1480;

    // ---- Index dtype probe + conversion ----
    probe_kernel<<<1, 1>>>((const unsigned*)dst, E);
    convert_kernel<<<egrid, TPB>>>(src, dst, E, N);

    // ---- CSR build (reused by both layers) ----
    hist_zero_kernel<<<ngrid, TPB>>>(hist, N);
    hist_kernel<<<egrid, TPB>>>(hist, E);
    csr_scan1_kernel<<<ngrid, TPB>>>(hist, N);
    csr_scan2_kernel<<<1, MAXB>>>(ngrid);
    csr_scan3_kernel<<<ngrid, TPB>>>(cur, N, E);
    csr_fill_kernel<<<egrid, TPB>>>(cur, E);

    // ---- Layer 1 ----
    gather_kernel<<<ggrid, TPB>>>(x, N, /*use_h1=*/0);
    gemm_kernel<<<mgrid, TPB>>>(x, Ws1, Wn1, b1, out, N, ntiles,
                                /*use_h1=*/0, /*out_is_h1=*/1);

    // ---- Layer 2 ----
    gather_kernel<<<ggrid, TPB>>>(x, N, /*use_h1=*/1);
    gemm_kernel<<<mgrid, TPB>>>(x, Ws2, Wn2, b2, out, N, ntiles,
                                /*use_h1=*/1, /*out_is_h1=*/0);
}

// round 7
// speedup vs baseline: 1.5060x; 1.5060x over previous
#include <cuda_runtime.h>
#include <cstdint>

#define D 64
#define MAXN 100000
#define MAXE 1600000
#define MAXB 512   // max scan blocks: ceil(100000/256)=391 <= 512

// Scratch (device globals — PLAIN loads/stores only; atomics on module
// globals trap with cudaErrorInvalidAddressSpace in this environment).
__device__ __align__(16) float g_hn[(size_t)MAXN * D];   // neighbor mean
__device__ __align__(16) float g_h1[(size_t)MAXN * D];   // layer-1 output
__device__ int g_off[MAXN + 1];    // CSR row offsets
__device__ int g_bsum[MAXB];       // scan block sums
__device__ int g_eidx[MAXE];       // CSR column indices (source nodes)
__device__ int g_src[MAXE];        // converted src indices (int32)
__device__ int g_dst[MAXE];        // converted dst indices (int32)
__device__ int g_is64;             // 1 if index buffers are int64

// Atomics only on d_out scratch (harness-allocated):
//   scratch[0..N) histogram, scratch[N..2N) fill cursors.
// Layer-2 GEMM overwrites all of d_out afterwards.

// ---------------------------------------------------------------------------
// Dtype probe (parallel): int64 indices < 2^31 have all odd words zero.
// ---------------------------------------------------------------------------
__global__ void probe_kernel(const unsigned* __restrict__ raw, int E) {
    __shared__ int s[256];
    int t = threadIdx.x;
    int nprobe = E < 4096 ? E : 4096;
    int any = 0;
    for (int i = t; i < nprobe; i += 256) any |= (int)raw[2 * i + 1];
    s[t] = any;
    __syncthreads();
    #pragma unroll
    for (int off = 128; off > 0; off >>= 1) {
        if (t < off) s[t] |= s[t + off];
        __syncthreads();
    }
    if (t == 0) g_is64 = (s[0] == 0) ? 1 : 0;
}

// Convert + clamp indices AND build dst histogram in one pass.
__global__ void convert_hist_kernel(const void* __restrict__ srcp,
                                    const void* __restrict__ dstp,
                                    int* __restrict__ hist, int E, int N) {
    int e = blockIdx.x * blockDim.x + threadIdx.x;
    if (e >= E) return;
    int s, d;
    if (g_is64) {
        s = (int)((const long long*)srcp)[e];
        d = (int)((const long long*)dstp)[e];
    } else {
        s = ((const int*)srcp)[e];
        d = ((const int*)dstp)[e];
    }
    s = s < 0 ? 0 : (s >= N ? N - 1 : s);
    d = d < 0 ? 0 : (d >= N ? N - 1 : d);
    g_src[e] = s;
    g_dst[e] = d;
    atomicAdd(&hist[d], 1);
}

__global__ void hist_zero_kernel(int* __restrict__ scratch, int N) {
    int i = blockIdx.x * blockDim.x + threadIdx.x;
    if (i < N) scratch[i] = 0;
}

// Per-block exclusive scan of counts (Hillis-Steele over 256)
__global__ void csr_scan1_kernel(const int* __restrict__ scratch, int N) {
    __shared__ int buf[2][256];
    int t = threadIdx.x;
    int i = blockIdx.x * 256 + t;
    int v = (i < N) ? scratch[i] : 0;
    buf[0][t] = v;
    __syncthreads();
    int p = 0;
    #pragma unroll
    for (int off = 1; off < 256; off <<= 1) {
        int val = buf[p][t] + ((t >= off) ? buf[p][t - off] : 0);
        buf[1 - p][t] = val;
        __syncthreads();
        p = 1 - p;
    }
    int incl = buf[p][t];
    if (i < N) g_off[i] = incl - v;
    if (t == 255) g_bsum[blockIdx.x] = incl;
}

// Single-block exclusive scan of block sums (nb <= 512)
__global__ void csr_scan2_kernel(int nb) {
    __shared__ int buf[2][MAXB];
    int t = threadIdx.x;
    int v = (t < nb) ? g_bsum[t] : 0;
    buf[0][t] = v;
    __syncthreads();
    int p = 0;
    for (int off = 1; off < MAXB; off <<= 1) {
        int val = buf[p][t] + ((t >= off) ? buf[p][t - off] : 0);
        buf[1 - p][t] = val;
        __syncthreads();
        p = 1 - p;
    }
    int incl = buf[p][t];
    if (t < nb) g_bsum[t] = incl - v;
}

// Add block prefixes; init fill cursors; write g_off[N]
__global__ void csr_scan3_kernel(int* __restrict__ cur, int N, int E) {
    int i = blockIdx.x * blockDim.x + threadIdx.x;
    if (i < N) {
        int o = g_off[i] + g_bsum[i >> 8];
        g_off[i] = o;
        cur[i] = o;
    }
    if (i == 0) g_off[N] = E;
}

// Fill CSR column indices (int atomics on harness-allocated cursors)
__global__ void csr_fill_kernel(int* __restrict__ cur, int E) {
    int e = blockIdx.x * blockDim.x + threadIdx.x;
    if (e < E) {
        int pos = atomicAdd(&cur[g_dst[e]], 1);
        if (pos >= 0 && pos < MAXE) g_eidx[pos] = g_src[e];
    }
}

// ---------------------------------------------------------------------------
// Gather-mean: 16 threads per node, each owns one float4 column chunk.
// ---------------------------------------------------------------------------
__global__ void gather_kernel(const float* __restrict__ x, int N, int use_h1) {
    const float* h = use_h1 ? (const float*)g_h1 : x;
    int gid = blockIdx.x * blockDim.x + threadIdx.x;
    int n = gid >> 4;
    if (n >= N) return;
    int c = (gid & 15) << 2;

    int beg = g_off[n];
    int end = g_off[n + 1];

    float ax = 0.0f, ay = 0.0f, az = 0.0f, aw = 0.0f;
    int j = beg;
    // 2x unroll for MLP
    for (; j + 1 < end; j += 2) {
        int s0 = g_eidx[j], s1 = g_eidx[j + 1];
        float4 v0 = *reinterpret_cast<const float4*>(h + ((size_t)s0 << 6) + c);
        float4 v1 = *reinterpret_cast<const float4*>(h + ((size_t)s1 << 6) + c);
        ax += v0.x + v1.x; ay += v0.y + v1.y;
        az += v0.z + v1.z; aw += v0.w + v1.w;
    }
    if (j < end) {
        int s0 = g_eidx[j];
        float4 v0 = *reinterpret_cast<const float4*>(h + ((size_t)s0 << 6) + c);
        ax += v0.x; ay += v0.y; az += v0.z; aw += v0.w;
    }
    float inv = 1.0f / fmaxf((float)(end - beg), 1.0f);
    float4 r;
    r.x = ax * inv; r.y = ay * inv; r.z = az * inv; r.w = aw * inv;
    *reinterpret_cast<float4*>(g_hn + ((size_t)n << 6) + c) = r;
}

// ---------------------------------------------------------------------------
// GEMM v2: out[r][c] = sum_k in[r][k]*Ws[k][c] + hn[r][k]*Wn[k][c] + b[c]
// 64-row x 64-col tile, 256 threads, 4x4 register blocking, all-LDS.128
// smem traffic. Dynamic smem: sWs|sWn|sx|sh = 4*16KB = 64KB.
// ---------------------------------------------------------------------------
__global__ void gemm_kernel(const float* __restrict__ x,
                            const float* __restrict__ Ws,
                            const float* __restrict__ Wn,
                            const float* __restrict__ b,
                            float* __restrict__ o,
                            int N, int ntiles, int use_h1, int out_is_h1) {
    const float* in = use_h1 ? (const float*)g_h1 : x;
    float* out      = out_is_h1 ? (float*)g_h1 : o;

    extern __shared__ float sm[];
    float* sWs = sm;              // [64][64]
    float* sWn = sm + 4096;       // [64][64]
    float* sx  = sm + 8192;       // [64][64]
    float* sh  = sm + 12288;      // [64][64]

    const int t = threadIdx.x;

    // Stage both weight matrices once per block (float4)
    for (int i = t; i < 1024; i += 256) {
        reinterpret_cast<float4*>(sWs)[i] =
            reinterpret_cast<const float4*>(Ws)[i];
        reinterpret_cast<float4*>(sWn)[i] =
            reinterpret_cast<const float4*>(Wn)[i];
    }

    const int cg = (t & 15) << 2;   // column group: 4 consecutive cols
    const int rg = (t >> 4) << 2;   // row group: 4 rows
    const float4 bias = *reinterpret_cast<const float4*>(b + cg);

    for (int tile = blockIdx.x; tile < ntiles; tile += gridDim.x) {
        int base = tile * 64;
        __syncthreads();

        // Stage 64 rows of in and hn (float4 over k)
        for (int i = t; i < 1024; i += 256) {
            int rr = i >> 4;            // 0..63
            int kk4 = (i & 15);         // float4 index within row
            int row = base + rr;
            float4 vx = make_float4(0.f, 0.f, 0.f, 0.f);
            float4 vh = vx;
            if (row < N) {
                vx = reinterpret_cast<const float4*>(in + ((size_t)row << 6))[kk4];
                vh = reinterpret_cast<const float4*>(g_hn + ((size_t)row << 6))[kk4];
            }
            reinterpret_cast<float4*>(sx + rr * 64)[kk4] = vx;
            reinterpret_cast<float4*>(sh + rr * 64)[kk4] = vh;
        }
        __syncthreads();

        float acc[4][4];
        #pragma unroll
        for (int r = 0; r < 4; r++)
            #pragma unroll
            for (int c = 0; c < 4; c++) acc[r][c] = 0.0f;

        #pragma unroll 4
        for (int k0 = 0; k0 < 64; k0 += 4) {
            float4 xv[4], hv[4];
            #pragma unroll
            for (int r = 0; r < 4; r++) {
                xv[r] = *reinterpret_cast<const float4*>(sx + (rg + r) * 64 + k0);
                hv[r] = *reinterpret_cast<const float4*>(sh + (rg + r) * 64 + k0);
            }
            #pragma unroll
            for (int kk = 0; kk < 4; kk++) {
                float4 ws = *reinterpret_cast<const float4*>(sWs + (k0 + kk) * 64 + cg);
                float4 wn = *reinterpret_cast<const float4*>(sWn + (k0 + kk) * 64 + cg);
                #pragma unroll
                for (int r = 0; r < 4; r++) {
                    float vx = reinterpret_cast<const float*>(&xv[r])[kk];
                    float vh = reinterpret_cast<const float*>(&hv[r])[kk];
                    acc[r][0] += vx * ws.x;  acc[r][0] += vh * wn.x;
                    acc[r][1] += vx * ws.y;  acc[r][1] += vh * wn.y;
                    acc[r][2] += vx * ws.z;  acc[r][2] += vh * wn.z;
                    acc[r][3] += vx * ws.w;  acc[r][3] += vh * wn.w;
                }
            }
        }

        #pragma unroll
        for (int r = 0; r < 4; r++) {
            int row = base + rg + r;
            if (row < N) {
                float4 v;
                v.x = acc[r][0] + bias.x;
                v.y = acc[r][1] + bias.y;
                v.z = acc[r][2] + bias.z;
                v.w = acc[r][3] + bias.w;
                *reinterpret_cast<float4*>(out + ((size_t)row << 6) + cg) = v;
            }
        }
    }
}

// ---------------------------------------------------------------------------
// Launch: probe/convert + CSR build + 2 SAGE layers.
// Inputs: x, src, dst, W_self1, W_neigh1, b1, W_self2, W_neigh2, b2
// ---------------------------------------------------------------------------
extern "C" void kernel_launch(void* const* d_in, const int* in_sizes, int n_in,
                              void* d_out, int out_size) {
    const float* x   = (const float*)d_in[0];
    const void*  src = d_in[1];
    const void*  dst = d_in[2];
    const float* Ws1 = (const float*)d_in[3];
    const float* Wn1 = (const float*)d_in[4];
    const float* b1  = (const float*)d_in[5];
    const float* Ws2 = (const float*)d_in[6];
    const float* Wn2 = (const float*)d_in[7];
    const float* b2  = (const float*)d_in[8];
    float* out = (float*)d_out;

    int N = in_sizes[0] / D;
    int E = in_sizes[1];

    int* hist = (int*)d_out;
    int* cur  = ((int*)d_out) + N;

    const int TPB = 256;
    int ngrid = (N + TPB - 1) / TPB;
    int egrid = (E + TPB - 1) / TPB;
    int ggrid = ((N * 16) + TPB - 1) / TPB;
    int ntiles = (N + 63) / 64;
    int mgrid = ntiles < 448 ? ntiles : 448;

    const int GEMM_SMEM = 65536 + 1024;
    cudaFuncSetAttribute(gemm_kernel,
                         cudaFuncAttributeMaxDynamicSharedMemorySize, GEMM_SMEM);

    // ---- Index dtype probe + conversion + histogram ----
    probe_kernel<<<1, 256>>>((const unsigned*)dst, E);
    hist_zero_kernel<<<ngrid, TPB>>>(hist, N);
    convert_hist_kernel<<<egrid, TPB>>>(src, dst, hist, E, N);

    // ---- CSR build (reused by both layers) ----
    csr_scan1_kernel<<<ngrid, TPB>>>(hist, N);
    csr_scan2_kernel<<<1, MAXB>>>(ngrid);
    csr_scan3_kernel<<<ngrid, TPB>>>(cur, N, E);
    csr_fill_kernel<<<egrid, TPB>>>(cur, E);

    // ---- Layer 1 ----
    gather_kernel<<<ggrid, TPB>>>(x, N, /*use_h1=*/0);
    gemm_kernel<<<mgrid, TPB, GEMM_SMEM>>>(x, Ws1, Wn1, b1, out, N, ntiles,
                                           /*use_h1=*/0, /*out_is_h1=*/1);

    // ---- Layer 2 ----
    gather_kernel<<<ggrid, TPB>>>(x, N, /*use_h1=*/1);
    gemm_kernel<<<mgrid, TPB, GEMM_SMEM>>>(x, Ws2, Wn2, b2, out, N, ntiles,
                                           /*use_h1=*/1, /*out_is_h1=*/0);
}